// round 14
// baseline (speedup 1.0000x reference)
#include <cuda_runtime.h>
#include <cstdint>

#define Nn 100000
#define Ee 1000000
#define GB3 ((Nn + 255) / 256)     /* 391 gemm blocks per graph (256-row tiles) */
#define SCB 196                    /* scan blocks: ceil(Nn/512) */

#define XSTR 68                    /* row stride: lane bank = 4*gid+tig, conflict-free */
#define WSTR 68
#define SM_X (256 * XSTR)          /* 17408 floats */
#define SM_W (64 * WSTR)           /* 4352 floats */
#define OFF_W1S (SM_X + SM_W)
#define OFF_B1S (OFF_W1S + 256)
#define SMEM_WORDS (OFF_B1S + 64)      /* 22080 words */
#define SMEM_BYTES (SMEM_WORDS * 4)    /* 88320 B -> 2 CTAs/SM, 32 warps */

// Scratch (device globals — no runtime allocation allowed)
__device__ float g_Yb[2][(size_t)Nn * 64];
__device__ float g_Hb[2][(size_t)Nn * 64];
__device__ float g_Fb[(size_t)Nn * 64];
__device__ float g_D[2][Nn];
__device__ float g_Wp[2][64 * 64];          // w2 @ W0
__device__ float g_bp[2][64];               // b2 @ W0
// CSR scratch
__device__ int g_cnt[2][Nn];
__device__ int g_rp[2][Nn + 1];
__device__ int g_wp[2][Nn];
__device__ int g_col[2][Ee];
__device__ int g_bs[2][256];

// ---------------------------------------------------------------------------
// tf32 helpers
// ---------------------------------------------------------------------------
__device__ __forceinline__ void split_tf32(float f, uint32_t& hi, uint32_t& lo) {
    asm("cvt.rna.tf32.f32 %0, %1;" : "=r"(hi) : "f"(f));
    float d = f - __uint_as_float(hi);
    asm("cvt.rna.tf32.f32 %0, %1;" : "=r"(lo) : "f"(d));
}

__device__ __forceinline__ void mma_tf32(float c[4], const uint32_t a[4], const uint32_t b[2]) {
    asm("mma.sync.aligned.m16n8k8.row.col.f32.tf32.tf32.f32 "
        "{%0,%1,%2,%3}, {%4,%5,%6,%7}, {%8,%9}, {%0,%1,%2,%3};"
        : "+f"(c[0]), "+f"(c[1]), "+f"(c[2]), "+f"(c[3])
        : "r"(a[0]), "r"(a[1]), "r"(a[2]), "r"(a[3]), "r"(b[0]), "r"(b[1]));
}

// ---------------------------------------------------------------------------
// Tensor-core GEMM body (R10-style in-loop splits) over Xs (256xK64, stride
// XSTR) and Wt (col-major 64x64, stride WSTR).
// 16 warps: 8m x 2n; per warp 2x4 m16n8 tiles; 3xTF32 (bb + bs + sb).
// ---------------------------------------------------------------------------
__device__ __forceinline__ void tf32_core(const float* Xs, const float* Wt,
                                          int tid, float c_[2][4][4]) {
    int lane = tid & 31, wid = tid >> 5;
    int gid = lane >> 2, tig = lane & 3;
    int m0 = (wid >> 1) * 32;      // 0..224
    int n0 = (wid & 1) * 32;

#pragma unroll
    for (int k0 = 0; k0 < 64; k0 += 8) {
        uint32_t ab[2][4], as_[2][4];
#pragma unroll
        for (int i = 0; i < 2; i++) {
            const float* base = Xs + (m0 + i * 16 + gid) * XSTR + k0 + tig;
            float f0 = base[0];
            float f1 = base[8 * XSTR];
            float f2 = base[4];
            float f3 = base[8 * XSTR + 4];
            split_tf32(f0, ab[i][0], as_[i][0]);
            split_tf32(f1, ab[i][1], as_[i][1]);
            split_tf32(f2, ab[i][2], as_[i][2]);
            split_tf32(f3, ab[i][3], as_[i][3]);
        }
        uint32_t bb[4][2], bs[4][2];
#pragma unroll
        for (int j = 0; j < 4; j++) {
            const float* base = Wt + (n0 + j * 8 + gid) * WSTR + k0 + tig;
            float g0 = base[0];
            float g1 = base[4];
            split_tf32(g0, bb[j][0], bs[j][0]);
            split_tf32(g1, bb[j][1], bs[j][1]);
        }
#pragma unroll
        for (int i = 0; i < 2; i++)
#pragma unroll
            for (int j = 0; j < 4; j++) {
                mma_tf32(c_[i][j], ab[i], bb[j]);
                mma_tf32(c_[i][j], ab[i], bs[j]);
                mma_tf32(c_[i][j], as_[i], bb[j]);
            }
    }
}

// Fill Wt (col-major, stride WSTR) from row-major W[64][64] — 512 threads
__device__ __forceinline__ void fill_wt(float* Wt, const float* __restrict__ W, int tid) {
#pragma unroll
    for (int t = 0; t < 8; t++) {
        int idx = tid + t * 512;
        int k = idx >> 6, n = idx & 63;
        Wt[n * WSTR + k] = __ldg(W + idx);
    }
}

// Fill Xs (stride XSTR) as plain copy of in[(row0..row0+255)][64] — 512 threads
__device__ __forceinline__ void fill_copy(float* Xs, const float* __restrict__ in,
                                          int tid, int row0) {
#pragma unroll
    for (int t = 0; t < 8; t++) {
        int lin = tid + t * 512;
        int r = lin >> 4, c4 = lin & 15;
        float4 v = make_float4(0.f, 0.f, 0.f, 0.f);
        if (row0 + r < Nn) v = ((const float4*)in)[(size_t)(row0 + r) * 16 + c4];
        *(float4*)(Xs + r * XSTR + c4 * 4) = v;
    }
}

// Epilogue: write (c + bias) * dinv to out (bias/dinv optional)
__device__ __forceinline__ void epilogue(const float c_[2][4][4], int tid, int row0,
                                         const float* __restrict__ bias,
                                         const float* __restrict__ dinv,
                                         float* __restrict__ out) {
    int lane = tid & 31, wid = tid >> 5;
    int gid = lane >> 2, tig = lane & 3;
    int m0 = (wid >> 1) * 32;
    int n0 = (wid & 1) * 32;
#pragma unroll
    for (int i = 0; i < 2; i++) {
        int r0 = row0 + m0 + i * 16 + gid;
        int r1 = r0 + 8;
        float d0 = (r0 < Nn && dinv) ? dinv[r0] : 1.f;
        float d1 = (r1 < Nn && dinv) ? dinv[r1] : 1.f;
#pragma unroll
        for (int j = 0; j < 4; j++) {
            int cc = n0 + j * 8 + 2 * tig;
            float bx = 0.f, by = 0.f;
            if (bias) { float2 bv = *(const float2*)(bias + cc); bx = bv.x; by = bv.y; }
            if (r0 < Nn)
                *(float2*)(out + (size_t)r0 * 64 + cc) =
                    make_float2((c_[i][j][0] + bx) * d0, (c_[i][j][1] + by) * d0);
            if (r1 < Nn)
                *(float2*)(out + (size_t)r1 * 64 + cc) =
                    make_float2((c_[i][j][2] + bx) * d1, (c_[i][j][3] + by) * d1);
        }
    }
}

// ---------------------------------------------------------------------------
// Front GEMM (both graphs): Y = (relu(x@w1+b1) @ Wp + bp) * dinv
// ---------------------------------------------------------------------------
__global__ __launch_bounds__(512) void frontT_k(
    const float* __restrict__ x0, const float* __restrict__ x1,
    const float* __restrict__ w10, const float* __restrict__ w11,
    const float* __restrict__ b10, const float* __restrict__ b11,
    const float* __restrict__ Wpb, const float* __restrict__ bpb,
    const float* __restrict__ Dinvb, float* __restrict__ Yb) {
    extern __shared__ float sm[];
    float* Xs = sm;
    float* Wt = sm + SM_X;
    float* W1s = sm + OFF_W1S;
    float* B1s = sm + OFF_B1S;

    int g = blockIdx.y;
    const float* x  = g ? x1 : x0;
    const float* w1 = g ? w11 : w10;
    const float* b1 = g ? b11 : b10;
    int tid = threadIdx.x;
    int row0 = blockIdx.x * 256;

    fill_wt(Wt, Wpb + g * 4096, tid);
    if (tid < 256) W1s[tid] = __ldg(w1 + tid);
    if (tid < 64)  B1s[tid] = __ldg(b1 + tid);
    __syncthreads();

    // encoder fill: Xs[r,c] = relu(b1[c] + sum_{k<4} x[r,k]*w1[k,c])
#pragma unroll
    for (int t = 0; t < 8; t++) {
        int lin = tid + t * 512;
        int r = lin >> 4;
        int c = (lin & 15) * 4;
        float4 v = make_float4(0.f, 0.f, 0.f, 0.f);
        if (row0 + r < Nn) {
            float4 xv = __ldg((const float4*)x + (row0 + r));
            v.x = fmaxf(B1s[c+0] + xv.x*W1s[c+0] + xv.y*W1s[64+c+0] + xv.z*W1s[128+c+0] + xv.w*W1s[192+c+0], 0.f);
            v.y = fmaxf(B1s[c+1] + xv.x*W1s[c+1] + xv.y*W1s[64+c+1] + xv.z*W1s[128+c+1] + xv.w*W1s[192+c+1], 0.f);
            v.z = fmaxf(B1s[c+2] + xv.x*W1s[c+2] + xv.y*W1s[64+c+2] + xv.z*W1s[128+c+2] + xv.w*W1s[192+c+2], 0.f);
            v.w = fmaxf(B1s[c+3] + xv.x*W1s[c+3] + xv.y*W1s[64+c+3] + xv.z*W1s[128+c+3] + xv.w*W1s[192+c+3], 0.f);
        }
        *(float4*)(Xs + r * XSTR + c) = v;
    }
    __syncthreads();

    float c_[2][4][4];
#pragma unroll
    for (int i = 0; i < 2; i++)
#pragma unroll
        for (int j = 0; j < 4; j++)
#pragma unroll
            for (int q = 0; q < 4; q++) c_[i][j][q] = 0.f;

    tf32_core(Xs, Wt, tid, c_);
    epilogue(c_, tid, row0, bpb + g * 64, Dinvb + g * Nn,
             Yb + (size_t)g * Nn * 64);
}

// ---------------------------------------------------------------------------
// GCN GEMM (both graphs): Y = (H @ W) * dinv     (H already has relu/bias)
// ---------------------------------------------------------------------------
__global__ __launch_bounds__(512) void gcnT_k(
    const float* __restrict__ Hb,
    const float* __restrict__ W0, const float* __restrict__ W1,
    const float* __restrict__ Dinvb, float* __restrict__ Yb) {
    extern __shared__ float sm[];
    float* Xs = sm;
    float* Wt = sm + SM_X;

    int g = blockIdx.y;
    int tid = threadIdx.x;
    int row0 = blockIdx.x * 256;

    fill_wt(Wt, g ? W1 : W0, tid);
    fill_copy(Xs, Hb + (size_t)g * Nn * 64, tid, row0);
    __syncthreads();

    float c_[2][4][4];
#pragma unroll
    for (int i = 0; i < 2; i++)
#pragma unroll
        for (int j = 0; j < 4; j++)
#pragma unroll
            for (int q = 0; q < 4; q++) c_[i][j][q] = 0.f;

    tf32_core(Xs, Wt, tid, c_);
    epilogue(c_, tid, row0, nullptr, Dinvb + g * Nn, Yb + (size_t)g * Nn * 64);
}

// ---------------------------------------------------------------------------
// Fusion GEMM: F = [H_g0, H_g1] @ fw1 + fb1     (K=128 via two phases)
// ---------------------------------------------------------------------------
__global__ __launch_bounds__(512) void fusionT_k(
    const float* __restrict__ Hb, const float* __restrict__ fw1,
    const float* __restrict__ fb1, float* __restrict__ Fb) {
    extern __shared__ float sm[];
    float* Xs = sm;
    float* Wt = sm + SM_X;

    int tid = threadIdx.x;
    int row0 = blockIdx.x * 256;

    float c_[2][4][4];
#pragma unroll
    for (int i = 0; i < 2; i++)
#pragma unroll
        for (int j = 0; j < 4; j++)
#pragma unroll
            for (int q = 0; q < 4; q++) c_[i][j][q] = 0.f;

#pragma unroll
    for (int ph = 0; ph < 2; ph++) {
        fill_wt(Wt, fw1 + ph * 4096, tid);
        fill_copy(Xs, Hb + (size_t)ph * Nn * 64, tid, row0);
        __syncthreads();
        tf32_core(Xs, Wt, tid, c_);
        __syncthreads();
    }
    epilogue(c_, tid, row0, fb1, nullptr, Fb);
}

// ---------------------------------------------------------------------------
// CSR build: histogram -> exclusive scan -> placement fill
// ---------------------------------------------------------------------------
__global__ void hist_k(const int* __restrict__ e0, const int* __restrict__ e1,
                       int* __restrict__ c) {
    int e = blockIdx.x * blockDim.x + threadIdx.x;
    if (e < Ee) {
        atomicAdd(c + __ldg(e0 + Ee + e), 1);
        atomicAdd(c + Nn + __ldg(e1 + Ee + e), 1);
    }
}

__global__ void scan1_k(const int* __restrict__ cnt, int* __restrict__ rp,
                        int* __restrict__ bs) {
    int g = blockIdx.y;
    __shared__ int sh[512];
    int idx = blockIdx.x * 512 + threadIdx.x;
    int v = (idx < Nn) ? cnt[g * Nn + idx] : 0;
    sh[threadIdx.x] = v;
    __syncthreads();
#pragma unroll
    for (int o = 1; o < 512; o <<= 1) {
        int t = (threadIdx.x >= o) ? sh[threadIdx.x - o] : 0;
        __syncthreads();
        sh[threadIdx.x] += t;
        __syncthreads();
    }
    if (idx < Nn) rp[g * (Nn + 1) + idx] = sh[threadIdx.x];
    if (threadIdx.x == 511) bs[g * 256 + blockIdx.x] = sh[511];
}

__global__ void scan2_k(int* __restrict__ bs) {
    int g = blockIdx.x;
    __shared__ int sh[256];
    int v = (threadIdx.x < SCB) ? bs[g * 256 + threadIdx.x] : 0;
    sh[threadIdx.x] = v;
    __syncthreads();
#pragma unroll
    for (int o = 1; o < 256; o <<= 1) {
        int t = (threadIdx.x >= o) ? sh[threadIdx.x - o] : 0;
        __syncthreads();
        sh[threadIdx.x] += t;
        __syncthreads();
    }
    bs[g * 256 + threadIdx.x] = sh[threadIdx.x] - v;  // exclusive
}

__global__ void scan3_k(const int* __restrict__ cnt, int* __restrict__ rp,
                        const int* __restrict__ bs, int* __restrict__ wp) {
    int g = blockIdx.y;
    int idx = blockIdx.x * 512 + threadIdx.x;
    if (idx < Nn) {
        int ex = rp[g * (Nn + 1) + idx] - cnt[g * Nn + idx] + bs[g * 256 + blockIdx.x];
        rp[g * (Nn + 1) + idx] = ex;
        wp[g * Nn + idx] = ex;
    }
    if (idx == 0) rp[g * (Nn + 1) + Nn] = Ee;
}

__global__ void fill_k(const int* __restrict__ e0, const int* __restrict__ e1,
                       int* __restrict__ wp, int* __restrict__ col) {
    int e = blockIdx.x * blockDim.x + threadIdx.x;
    if (e >= Ee) return;
    {
        int dst = __ldg(e0 + Ee + e);
        int pos = atomicAdd(wp + dst, 1);
        col[pos] = __ldg(e0 + e);
    }
    {
        int dst = __ldg(e1 + Ee + e);
        int pos = atomicAdd(wp + Nn + dst, 1);
        col[Ee + pos] = __ldg(e1 + e);
    }
}

__global__ void dinv2_k(const int* __restrict__ rp, float* __restrict__ d) {
    int g = blockIdx.y;
    int i = blockIdx.x * blockDim.x + threadIdx.x;
    if (i < Nn) {
        int deg = rp[g * (Nn + 1) + i + 1] - rp[g * (Nn + 1) + i];
        d[g * Nn + i] = rsqrtf((float)deg + 1.f);
    }
}

// ---------------------------------------------------------------------------
// CSR aggregation + fused GCN epilogue, both graphs (grid.y = g):
//   H[n,:] = relu(dinv[n]*(sum_{src in adj(n)} Y[src,:] + Y[n,:]) + bias[:])
// ---------------------------------------------------------------------------
__global__ __launch_bounds__(256) void aggfuse2_k(
    const float* __restrict__ yb, const int* __restrict__ rpb,
    const int* __restrict__ colb, const float* __restrict__ Dinvb,
    const float* __restrict__ bias0, const float* __restrict__ bias1,
    float* __restrict__ Hb) {
    int g = blockIdx.y;
    const float* y = yb + (size_t)g * Nn * 64;
    const int* rp = rpb + g * (Nn + 1);
    const int* col = colb + (size_t)g * Ee;
    const float* bias = g ? bias1 : bias0;
    float* out = Hb + (size_t)g * Nn * 64;

    int node = blockIdx.x * 16 + (threadIdx.x >> 4);
    if (node >= Nn) return;
    int j = (threadIdx.x & 15) * 4;
    int b = __ldg(rp + node), e = __ldg(rp + node + 1);

    // self term
    float4 s0 = *(const float4*)(y + (size_t)node * 64 + j);
    float4 s1 = make_float4(0.f, 0.f, 0.f, 0.f);
    int i = b;
    for (; i + 2 <= e; i += 2) {
        int a0 = __ldg(col + i), a1 = __ldg(col + i + 1);
        float4 v0 = *(const float4*)(y + (size_t)a0 * 64 + j);
        float4 v1 = *(const float4*)(y + (size_t)a1 * 64 + j);
        s0.x += v0.x; s0.y += v0.y; s0.z += v0.z; s0.w += v0.w;
        s1.x += v1.x; s1.y += v1.y; s1.z += v1.z; s1.w += v1.w;
    }
    if (i < e) {
        int a0 = __ldg(col + i);
        float4 v0 = *(const float4*)(y + (size_t)a0 * 64 + j);
        s0.x += v0.x; s0.y += v0.y; s0.z += v0.z; s0.w += v0.w;
    }
    s0.x += s1.x; s0.y += s1.y; s0.z += s1.z; s0.w += s1.w;

    float dv = __ldg(Dinvb + g * Nn + node);
    float4 bv = __ldg((const float4*)(bias + j));
    float4 o;
    o.x = fmaxf(fmaf(dv, s0.x, bv.x), 0.f);
    o.y = fmaxf(fmaf(dv, s0.y, bv.y), 0.f);
    o.z = fmaxf(fmaf(dv, s0.z, bv.z), 0.f);
    o.w = fmaxf(fmaf(dv, s0.w, bv.w), 0.f);
    *(float4*)(out + (size_t)node * 64 + j) = o;
}

// ---------------------------------------------------------------------------
// Tiny precompute: Wp[g] = w2 @ cw[0];  bp[g] = b2 @ cw[0]
// ---------------------------------------------------------------------------
__global__ void prep_k(const float* __restrict__ w2a, const float* __restrict__ b2a,
                       const float* __restrict__ cwa,
                       const float* __restrict__ w2b, const float* __restrict__ b2b,
                       const float* __restrict__ cwb,
                       float* __restrict__ wp, float* __restrict__ bp) {
    int g = blockIdx.x;
    const float* w2 = g ? w2b : w2a;
    const float* b2 = g ? b2b : b2a;
    const float* cw = g ? cwb : cwa;
    __shared__ float A[4096], B[4096];
    int tid = threadIdx.x;
#pragma unroll
    for (int t = 0; t < 16; t++) {
        A[tid + t * 256] = w2[tid + t * 256];
        B[tid + t * 256] = cw[tid + t * 256];
    }
    __syncthreads();
    float* WP = wp + g * 4096;
#pragma unroll
    for (int t = 0; t < 16; t++) {
        int idx = tid + t * 256;
        int i = idx >> 6, j = idx & 63;
        float s = 0.f;
#pragma unroll 16
        for (int k = 0; k < 64; k++) s = fmaf(A[i * 64 + k], B[k * 64 + j], s);
        WP[idx] = s;
    }
    if (tid < 64) {
        float s = 0.f;
        for (int k = 0; k < 64; k++) s = fmaf(b2[k], B[k * 64 + tid], s);
        bp[g * 64 + tid] = s;
    }
}

// ---------------------------------------------------------------------------
// Head: fused = relu(h1) @ fw2 + fb2; feats = fused@ow+ob; types = fused@cw+cb
// ---------------------------------------------------------------------------
__global__ __launch_bounds__(256) void head_k(
    const float* __restrict__ h1, const float* __restrict__ fw2, const float* __restrict__ fb2,
    const float* __restrict__ ow, const float* __restrict__ ob,
    const float* __restrict__ cw, const float* __restrict__ cb,
    float* __restrict__ outF, float* __restrict__ outT) {
    __shared__ float Xs[64 * 64];
    __shared__ float Ws[64 * 64];
    int tid = threadIdx.x;
    int row0 = blockIdx.x * 64;
    size_t base = (size_t)row0 * 64;

#pragma unroll
    for (int t = 0; t < 16; t++) Ws[tid + t * 256] = fw2[tid + t * 256];
#pragma unroll
    for (int t = 0; t < 16; t++) {
        int lin = tid + t * 256;
        int r = lin >> 6;
        Xs[lin] = (row0 + r < Nn) ? fmaxf(h1[base + lin], 0.f) : 0.f;
    }
    __syncthreads();

    int cx = (tid & 15) * 4;
    int ry = (tid >> 4) * 4;
    float acc[4][4];
#pragma unroll
    for (int i = 0; i < 4; i++)
#pragma unroll
        for (int j = 0; j < 4; j++) acc[i][j] = 0.f;

#pragma unroll
    for (int k0 = 0; k0 < 64; k0 += 4) {
        float4 w0 = *(const float4*)(Ws + (k0 + 0) * 64 + cx);
        float4 w1 = *(const float4*)(Ws + (k0 + 1) * 64 + cx);
        float4 w2 = *(const float4*)(Ws + (k0 + 2) * 64 + cx);
        float4 w3 = *(const float4*)(Ws + (k0 + 3) * 64 + cx);
#pragma unroll
        for (int i = 0; i < 4; i++) {
            float4 a = *(const float4*)(Xs + (ry + i) * 64 + k0);
            acc[i][0] = fmaf(a.x, w0.x, fmaf(a.y, w1.x, fmaf(a.z, w2.x, fmaf(a.w, w3.x, acc[i][0]))));
            acc[i][1] = fmaf(a.x, w0.y, fmaf(a.y, w1.y, fmaf(a.z, w2.y, fmaf(a.w, w3.y, acc[i][1]))));
            acc[i][2] = fmaf(a.x, w0.z, fmaf(a.y, w1.z, fmaf(a.z, w2.z, fmaf(a.w, w3.z, acc[i][2]))));
            acc[i][3] = fmaf(a.x, w0.w, fmaf(a.y, w1.w, fmaf(a.z, w2.w, fmaf(a.w, w3.w, acc[i][3]))));
        }
    }
    __syncthreads();

    float4 bb = *(const float4*)(fb2 + cx);
#pragma unroll
    for (int i = 0; i < 4; i++) {
        Xs[(ry + i) * 64 + cx + 0] = acc[i][0] + bb.x;
        Xs[(ry + i) * 64 + cx + 1] = acc[i][1] + bb.y;
        Xs[(ry + i) * 64 + cx + 2] = acc[i][2] + bb.z;
        Xs[(ry + i) * 64 + cx + 3] = acc[i][3] + bb.w;
    }
#pragma unroll
    for (int t = 0; t < 8; t++) Ws[tid + t * 256] = ow[tid + t * 256];  // 64x32
    if (tid < 128) Ws[2048 + tid] = cw[tid];                             // 64x2
    __syncthreads();

    int c = tid & 31;
    int rb = (tid >> 5) * 8;
    for (int rr = 0; rr < 8; rr++) {
        int r = rb + rr;
        float a = __ldg(ob + c);
#pragma unroll 16
        for (int k = 0; k < 64; k++) a += Xs[r * 64 + k] * Ws[k * 32 + c];
        if (row0 + r < Nn) outF[(size_t)(row0 + r) * 32 + c] = a;
    }
    if (tid < 128) {
        int r = tid >> 1, cc = tid & 1;
        float a = __ldg(cb + cc);
#pragma unroll 16
        for (int k = 0; k < 64; k++) a += Xs[r * 64 + k] * Ws[2048 + k * 2 + cc];
        if (row0 + r < Nn) outT[(size_t)(row0 + r) * 2 + cc] = a;
    }
}

// ---------------------------------------------------------------------------
extern "C" void kernel_launch(void* const* d_in, const int* in_sizes, int n_in,
                              void* d_out, int out_size) {
    const float* xin[2] = {(const float*)d_in[0], (const float*)d_in[1]};
    const int* ei[2]    = {(const int*)d_in[2], (const int*)d_in[3]};
    const float* ew1[2] = {(const float*)d_in[4],  (const float*)d_in[10]};
    const float* eb1[2] = {(const float*)d_in[5],  (const float*)d_in[11]};
    const float* ew2[2] = {(const float*)d_in[6],  (const float*)d_in[12]};
    const float* eb2[2] = {(const float*)d_in[7],  (const float*)d_in[13]};
    const float* cw[2]  = {(const float*)d_in[8],  (const float*)d_in[14]};
    const float* cb[2]  = {(const float*)d_in[9],  (const float*)d_in[15]};
    const float* fw1 = (const float*)d_in[16];
    const float* fb1 = (const float*)d_in[17];
    const float* fw2 = (const float*)d_in[18];
    const float* fb2 = (const float*)d_in[19];
    const float* ow  = (const float*)d_in[20];
    const float* obv = (const float*)d_in[21];
    const float* clw = (const float*)d_in[22];
    const float* clb = (const float*)d_in[23];

    float *Yb, *Hb, *Fb, *Db, *Wp, *bp;
    int *cnt, *rp, *wpp, *colp, *bs;
    cudaGetSymbolAddress((void**)&Yb, g_Yb);
    cudaGetSymbolAddress((void**)&Hb, g_Hb);
    cudaGetSymbolAddress((void**)&Fb, g_Fb);
    cudaGetSymbolAddress((void**)&Db, g_D);
    cudaGetSymbolAddress((void**)&Wp, g_Wp);
    cudaGetSymbolAddress((void**)&bp, g_bp);
    cudaGetSymbolAddress((void**)&cnt, g_cnt);
    cudaGetSymbolAddress((void**)&rp, g_rp);
    cudaGetSymbolAddress((void**)&wpp, g_wp);
    cudaGetSymbolAddress((void**)&colp, g_col);
    cudaGetSymbolAddress((void**)&bs, g_bs);

    // Opt-in to >48KB dynamic smem (idempotent host calls, graph-safe)
    cudaFuncSetAttribute(frontT_k,  cudaFuncAttributeMaxDynamicSharedMemorySize, SMEM_BYTES);
    cudaFuncSetAttribute(gcnT_k,    cudaFuncAttributeMaxDynamicSharedMemorySize, SMEM_BYTES);
    cudaFuncSetAttribute(fusionT_k, cudaFuncAttributeMaxDynamicSharedMemorySize, SMEM_BYTES);

    // ---- CSR build (both graphs) ----
    cudaMemsetAsync(cnt, 0, 2 * Nn * sizeof(int));
    hist_k<<<(Ee + 255) / 256, 256>>>(ei[0], ei[1], cnt);
    scan1_k<<<dim3(SCB, 2), 512>>>(cnt, rp, bs);
    scan2_k<<<2, 256>>>(bs);
    scan3_k<<<dim3(SCB, 2), 512>>>(cnt, rp, bs, wpp);
    fill_k<<<(Ee + 255) / 256, 256>>>(ei[0], ei[1], wpp, colp);
    dinv2_k<<<dim3((Nn + 255) / 256, 2), 256>>>(rp, Db);
    prep_k<<<2, 256>>>(ew2[0], eb2[0], cw[0], ew2[1], eb2[1], cw[1], Wp, bp);

    const int AGB = (Nn + 15) / 16;
    const dim3 G2(GB3, 2), A2(AGB, 2);

    // Front (both graphs): Y = (relu(x@w1+b1) @ Wp + bp) * dinv
    frontT_k<<<G2, 512, SMEM_BYTES>>>(xin[0], xin[1], ew1[0], ew1[1], eb1[0], eb1[1],
                                      Wp, bp, Db, Yb);
    aggfuse2_k<<<A2, 256>>>(Yb, rp, colp, Db, cb[0], cb[1], Hb);

    // GCN layer 1: Y = (H @ cw[1]) * dinv
    gcnT_k<<<G2, 512, SMEM_BYTES>>>(Hb, cw[0] + 4096, cw[1] + 4096, Db, Yb);
    aggfuse2_k<<<A2, 256>>>(Yb, rp, colp, Db, cb[0] + 64, cb[1] + 64, Hb);

    // GCN layer 2: Y = (H @ cw[2]) * dinv
    gcnT_k<<<G2, 512, SMEM_BYTES>>>(Hb, cw[0] + 8192, cw[1] + 8192, Db, Yb);
    aggfuse2_k<<<A2, 256>>>(Yb, rp, colp, Db, cb[0] + 128, cb[1] + 128, Hb);

    // Fusion layer 1 (K=128, two phases): F = [H_g0, H_g1] @ fw1 + fb1
    fusionT_k<<<GB3, 512, SMEM_BYTES>>>(Hb, fw1, fb1, Fb);

    // Fusion layer 2 + both output heads
    head_k<<<(Nn + 63) / 64, 256>>>(Fb, fw2, fb2, ow, obv, clw, clb,
                                    (float*)d_out, (float*)d_out + (size_t)Nn * 32);
}

// round 15
// speedup vs baseline: 1.1214x; 1.1214x over previous
#include <cuda_runtime.h>
#include <cstdint>

#define Nn 100000
#define Ee 1000000
#define GB2 ((Nn + 127) / 128)     /* 782 gemm blocks per graph */
#define SCB 196                    /* scan blocks: ceil(Nn/512) */

#define XSTR 68                    /* Xs row stride: lane bank = 4*gid+tig, conflict-free */
#define WSTR 68
#define SM_X (128 * XSTR)          /* 8704 floats */
#define SM_W (64 * WSTR)           /* 4352 floats */
#define OFF_W1S (SM_X + SM_W)
#define OFF_B1S (OFF_W1S + 256)
#define SMEM_WORDS (OFF_B1S + 64)
#define SMEM_BYTES (SMEM_WORDS * 4)    /* 53504 B */

// Scratch (device globals — no runtime allocation allowed)
__device__ float g_Yb[2][(size_t)Nn * 64];
__device__ float g_Hb[2][(size_t)Nn * 64];
__device__ float g_D[2][Nn];
__device__ float g_Wp[2][64 * 64];          // w2 @ W0
__device__ float g_bp[2][64];               // b2 @ W0
// CSR scratch
__device__ int g_cnt[2][Nn];
__device__ int g_rp[2][Nn + 1];
__device__ int g_wp[2][Nn];
__device__ int g_col[2][Ee];
__device__ int g_bs[2][256];

// ---------------------------------------------------------------------------
// tf32 helpers
// ---------------------------------------------------------------------------
__device__ __forceinline__ void split_tf32(float f, uint32_t& hi, uint32_t& lo) {
    asm("cvt.rna.tf32.f32 %0, %1;" : "=r"(hi) : "f"(f));
    float d = f - __uint_as_float(hi);
    asm("cvt.rna.tf32.f32 %0, %1;" : "=r"(lo) : "f"(d));
}

__device__ __forceinline__ void mma_tf32(float c[4], const uint32_t a[4], const uint32_t b[2]) {
    asm("mma.sync.aligned.m16n8k8.row.col.f32.tf32.tf32.f32 "
        "{%0,%1,%2,%3}, {%4,%5,%6,%7}, {%8,%9}, {%0,%1,%2,%3};"
        : "+f"(c[0]), "+f"(c[1]), "+f"(c[2]), "+f"(c[3])
        : "r"(a[0]), "r"(a[1]), "r"(a[2]), "r"(a[3]), "r"(b[0]), "r"(b[1]));
}

// ---------------------------------------------------------------------------
// Tensor-core GEMM body (R10 config): Xs 128xK64 (stride XSTR), Wt col-major
// 64x64 (stride WSTR). 8 warps: 4m x 2n; per warp 2x4 m16n8; 3xTF32.
// ---------------------------------------------------------------------------
__device__ __forceinline__ void tf32_core(const float* Xs, const float* Wt,
                                          int tid, float c_[2][4][4]) {
    int lane = tid & 31, wid = tid >> 5;
    int gid = lane >> 2, tig = lane & 3;
    int m0 = (wid >> 1) * 32;
    int n0 = (wid & 1) * 32;

#pragma unroll
    for (int k0 = 0; k0 < 64; k0 += 8) {
        uint32_t ab[2][4], as_[2][4];
#pragma unroll
        for (int i = 0; i < 2; i++) {
            const float* base = Xs + (m0 + i * 16 + gid) * XSTR + k0 + tig;
            float f0 = base[0];
            float f1 = base[8 * XSTR];
            float f2 = base[4];
            float f3 = base[8 * XSTR + 4];
            split_tf32(f0, ab[i][0], as_[i][0]);
            split_tf32(f1, ab[i][1], as_[i][1]);
            split_tf32(f2, ab[i][2], as_[i][2]);
            split_tf32(f3, ab[i][3], as_[i][3]);
        }
        uint32_t bb[4][2], bs[4][2];
#pragma unroll
        for (int j = 0; j < 4; j++) {
            const float* base = Wt + (n0 + j * 8 + gid) * WSTR + k0 + tig;
            float g0 = base[0];
            float g1 = base[4];
            split_tf32(g0, bb[j][0], bs[j][0]);
            split_tf32(g1, bb[j][1], bs[j][1]);
        }
#pragma unroll
        for (int i = 0; i < 2; i++)
#pragma unroll
            for (int j = 0; j < 4; j++) {
                mma_tf32(c_[i][j], ab[i], bb[j]);
                mma_tf32(c_[i][j], ab[i], bs[j]);
                mma_tf32(c_[i][j], as_[i], bb[j]);
            }
    }
}

// Fill Wt (col-major, stride WSTR) from row-major W[64][64] — 256 threads
__device__ __forceinline__ void fill_wt(float* Wt, const float* __restrict__ W, int tid) {
#pragma unroll
    for (int t = 0; t < 16; t++) {
        int idx = tid + t * 256;
        int k = idx >> 6, n = idx & 63;
        Wt[n * WSTR + k] = __ldg(W + idx);
    }
}

// Fill Xs (stride XSTR) as copy of in[(row0..row0+127)][64] — 256 threads
__device__ __forceinline__ void fill_copy(float* Xs, const float* __restrict__ in,
                                          int tid, int row0) {
#pragma unroll
    for (int t = 0; t < 8; t++) {
        int lin = tid + t * 256;
        int r = lin >> 4, c4 = lin & 15;
        float4 v = make_float4(0.f, 0.f, 0.f, 0.f);
        if (row0 + r < Nn) v = ((const float4*)in)[(size_t)(row0 + r) * 16 + c4];
        *(float4*)(Xs + r * XSTR + c4 * 4) = v;
    }
}

// Epilogue: write (c + bias) * dinv to global out (bias/dinv optional)
__device__ __forceinline__ void epilogue(const float c_[2][4][4], int tid, int row0,
                                         const float* __restrict__ bias,
                                         const float* __restrict__ dinv,
                                         float* __restrict__ out) {
    int lane = tid & 31, wid = tid >> 5;
    int gid = lane >> 2, tig = lane & 3;
    int m0 = (wid >> 1) * 32;
    int n0 = (wid & 1) * 32;
#pragma unroll
    for (int i = 0; i < 2; i++) {
        int r0 = row0 + m0 + i * 16 + gid;
        int r1 = r0 + 8;
        float d0 = (r0 < Nn && dinv) ? dinv[r0] : 1.f;
        float d1 = (r1 < Nn && dinv) ? dinv[r1] : 1.f;
#pragma unroll
        for (int j = 0; j < 4; j++) {
            int cc = n0 + j * 8 + 2 * tig;
            float bx = 0.f, by = 0.f;
            if (bias) { float2 bv = *(const float2*)(bias + cc); bx = bv.x; by = bv.y; }
            if (r0 < Nn)
                *(float2*)(out + (size_t)r0 * 64 + cc) =
                    make_float2((c_[i][j][0] + bx) * d0, (c_[i][j][1] + by) * d0);
            if (r1 < Nn)
                *(float2*)(out + (size_t)r1 * 64 + cc) =
                    make_float2((c_[i][j][2] + bx) * d1, (c_[i][j][3] + by) * d1);
        }
    }
}

// Fragment write into smem tile (stride XSTR): v = f(c + bias), optional relu
__device__ __forceinline__ void frag_to_smem(const float c_[2][4][4], int tid,
                                             const float* __restrict__ bias,
                                             int doRelu, float* Xs) {
    int lane = tid & 31, wid = tid >> 5;
    int gid = lane >> 2, tig = lane & 3;
    int m0 = (wid >> 1) * 32;
    int n0 = (wid & 1) * 32;
#pragma unroll
    for (int i = 0; i < 2; i++) {
        int lr0 = m0 + i * 16 + gid;
        int lr1 = lr0 + 8;
#pragma unroll
        for (int j = 0; j < 4; j++) {
            int cc = n0 + j * 8 + 2 * tig;
            float2 bv = *(const float2*)(bias + cc);
            float a0 = c_[i][j][0] + bv.x, a1 = c_[i][j][1] + bv.y;
            float a2 = c_[i][j][2] + bv.x, a3 = c_[i][j][3] + bv.y;
            if (doRelu) {
                a0 = fmaxf(a0, 0.f); a1 = fmaxf(a1, 0.f);
                a2 = fmaxf(a2, 0.f); a3 = fmaxf(a3, 0.f);
            }
            *(float2*)(Xs + lr0 * XSTR + cc) = make_float2(a0, a1);
            *(float2*)(Xs + lr1 * XSTR + cc) = make_float2(a2, a3);
        }
    }
}

// ---------------------------------------------------------------------------
// Front GEMM (both graphs): Y = (relu(x@w1+b1) @ Wp + bp) * dinv
// ---------------------------------------------------------------------------
__global__ __launch_bounds__(256) void frontT_k(
    const float* __restrict__ x0, const float* __restrict__ x1,
    const float* __restrict__ w10, const float* __restrict__ w11,
    const float* __restrict__ b10, const float* __restrict__ b11,
    const float* __restrict__ Wpb, const float* __restrict__ bpb,
    const float* __restrict__ Dinvb, float* __restrict__ Yb) {
    extern __shared__ float sm[];
    float* Xs = sm;
    float* Wt = sm + SM_X;
    float* W1s = sm + OFF_W1S;
    float* B1s = sm + OFF_B1S;

    int g = blockIdx.y;
    const float* x  = g ? x1 : x0;
    const float* w1 = g ? w11 : w10;
    const float* b1 = g ? b11 : b10;
    int tid = threadIdx.x;
    int row0 = blockIdx.x * 128;

    fill_wt(Wt, Wpb + g * 4096, tid);
    if (tid < 256) W1s[tid] = __ldg(w1 + tid);
    if (tid < 64)  B1s[tid] = __ldg(b1 + tid);
    __syncthreads();

#pragma unroll
    for (int t = 0; t < 8; t++) {
        int lin = tid + t * 256;
        int r = lin >> 4;
        int c = (lin & 15) * 4;
        float4 v = make_float4(0.f, 0.f, 0.f, 0.f);
        if (row0 + r < Nn) {
            float4 xv = __ldg((const float4*)x + (row0 + r));
            v.x = fmaxf(B1s[c+0] + xv.x*W1s[c+0] + xv.y*W1s[64+c+0] + xv.z*W1s[128+c+0] + xv.w*W1s[192+c+0], 0.f);
            v.y = fmaxf(B1s[c+1] + xv.x*W1s[c+1] + xv.y*W1s[64+c+1] + xv.z*W1s[128+c+1] + xv.w*W1s[192+c+1], 0.f);
            v.z = fmaxf(B1s[c+2] + xv.x*W1s[c+2] + xv.y*W1s[64+c+2] + xv.z*W1s[128+c+2] + xv.w*W1s[192+c+2], 0.f);
            v.w = fmaxf(B1s[c+3] + xv.x*W1s[c+3] + xv.y*W1s[64+c+3] + xv.z*W1s[128+c+3] + xv.w*W1s[192+c+3], 0.f);
        }
        *(float4*)(Xs + r * XSTR + c) = v;
    }
    __syncthreads();

    float c_[2][4][4];
#pragma unroll
    for (int i = 0; i < 2; i++)
#pragma unroll
        for (int j = 0; j < 4; j++)
#pragma unroll
            for (int q = 0; q < 4; q++) c_[i][j][q] = 0.f;

    tf32_core(Xs, Wt, tid, c_);
    epilogue(c_, tid, row0, bpb + g * 64, Dinvb + g * Nn,
             Yb + (size_t)g * Nn * 64);
}

// ---------------------------------------------------------------------------
// GCN GEMM (both graphs): Y = (H @ W) * dinv
// ---------------------------------------------------------------------------
__global__ __launch_bounds__(256) void gcnT_k(
    const float* __restrict__ Hb,
    const float* __restrict__ W0, const float* __restrict__ W1,
    const float* __restrict__ Dinvb, float* __restrict__ Yb) {
    extern __shared__ float sm[];
    float* Xs = sm;
    float* Wt = sm + SM_X;

    int g = blockIdx.y;
    int tid = threadIdx.x;
    int row0 = blockIdx.x * 128;

    fill_wt(Wt, g ? W1 : W0, tid);
    fill_copy(Xs, Hb + (size_t)g * Nn * 64, tid, row0);
    __syncthreads();

    float c_[2][4][4];
#pragma unroll
    for (int i = 0; i < 2; i++)
#pragma unroll
        for (int j = 0; j < 4; j++)
#pragma unroll
            for (int q = 0; q < 4; q++) c_[i][j][q] = 0.f;

    tf32_core(Xs, Wt, tid, c_);
    epilogue(c_, tid, row0, nullptr, Dinvb + g * Nn, Yb + (size_t)g * Nn * 64);
}

// ---------------------------------------------------------------------------
// Fused fusion + head kernel:
//   F = [H_g0, H_g1] @ fw1 + fb1         (K=128, two tf32 phases)
//   fused = relu(F) @ fw2 + fb2          (K=64 tf32 phase, all in smem)
//   outF = fused @ ow + ob;  outT = fused @ cw + cb
// ---------------------------------------------------------------------------
__global__ __launch_bounds__(256) void fushead_k(
    const float* __restrict__ Hb, const float* __restrict__ fw1,
    const float* __restrict__ fb1, const float* __restrict__ fw2,
    const float* __restrict__ fb2, const float* __restrict__ ow,
    const float* __restrict__ ob, const float* __restrict__ cw,
    const float* __restrict__ cb,
    float* __restrict__ outF, float* __restrict__ outT) {
    extern __shared__ float sm[];
    float* Xs = sm;
    float* Wt = sm + SM_X;

    int tid = threadIdx.x;
    int row0 = blockIdx.x * 128;

    // ---- fusion layer 1: F (K=128 via two phases) ----
    float c_[2][4][4];
#pragma unroll
    for (int i = 0; i < 2; i++)
#pragma unroll
        for (int j = 0; j < 4; j++)
#pragma unroll
            for (int q = 0; q < 4; q++) c_[i][j][q] = 0.f;

#pragma unroll
    for (int ph = 0; ph < 2; ph++) {
        fill_wt(Wt, fw1 + ph * 4096, tid);
        fill_copy(Xs, Hb + (size_t)ph * Nn * 64, tid, row0);
        __syncthreads();
        tf32_core(Xs, Wt, tid, c_);
        __syncthreads();
    }

    // ---- relu(F + fb1) -> Xs; fw2 -> Wt ----
    frag_to_smem(c_, tid, fb1, 1, Xs);
    fill_wt(Wt, fw2, tid);
    __syncthreads();

    // ---- fusion layer 2: fused = relu(F) @ fw2 ----
#pragma unroll
    for (int i = 0; i < 2; i++)
#pragma unroll
        for (int j = 0; j < 4; j++)
#pragma unroll
            for (int q = 0; q < 4; q++) c_[i][j][q] = 0.f;
    tf32_core(Xs, Wt, tid, c_);
    __syncthreads();

    // ---- fused + fb2 -> Xs; head weights -> Wt ----
    frag_to_smem(c_, tid, fb2, 0, Xs);
#pragma unroll
    for (int t = 0; t < 8; t++) Wt[tid + t * 256] = __ldg(ow + tid + t * 256);  // 64x32
    if (tid < 128) Wt[2048 + tid] = __ldg(cw + tid);                             // 64x2
    __syncthreads();

    // ---- node_features: 128 rows x 32 cols, 16 rows per thread ----
    int c = tid & 31;
    int rb = (tid >> 5) * 16;
    for (int rr = 0; rr < 16; rr++) {
        int r = rb + rr;
        float a = __ldg(ob + c);
#pragma unroll 16
        for (int k = 0; k < 64; k++) a += Xs[r * XSTR + k] * Wt[k * 32 + c];
        if (row0 + r < Nn) outF[(size_t)(row0 + r) * 32 + c] = a;
    }
    // ---- node_types: 128 rows x 2 cols, 1 output per thread ----
    {
        int r = tid >> 1, cc = tid & 1;
        float a = __ldg(cb + cc);
#pragma unroll 16
        for (int k = 0; k < 64; k++) a += Xs[r * XSTR + k] * Wt[2048 + k * 2 + cc];
        if (row0 + r < Nn) outT[(size_t)(row0 + r) * 2 + cc] = a;
    }
}

// ---------------------------------------------------------------------------
// CSR build: histogram -> exclusive scan -> placement fill
// ---------------------------------------------------------------------------
__global__ void hist_k(const int* __restrict__ e0, const int* __restrict__ e1,
                       int* __restrict__ c) {
    int e = blockIdx.x * blockDim.x + threadIdx.x;
    if (e < Ee) {
        atomicAdd(c + __ldg(e0 + Ee + e), 1);
        atomicAdd(c + Nn + __ldg(e1 + Ee + e), 1);
    }
}

__global__ void scan1_k(const int* __restrict__ cnt, int* __restrict__ rp,
                        int* __restrict__ bs) {
    int g = blockIdx.y;
    __shared__ int sh[512];
    int idx = blockIdx.x * 512 + threadIdx.x;
    int v = (idx < Nn) ? cnt[g * Nn + idx] : 0;
    sh[threadIdx.x] = v;
    __syncthreads();
#pragma unroll
    for (int o = 1; o < 512; o <<= 1) {
        int t = (threadIdx.x >= o) ? sh[threadIdx.x - o] : 0;
        __syncthreads();
        sh[threadIdx.x] += t;
        __syncthreads();
    }
    if (idx < Nn) rp[g * (Nn + 1) + idx] = sh[threadIdx.x];
    if (threadIdx.x == 511) bs[g * 256 + blockIdx.x] = sh[511];
}

__global__ void scan2_k(int* __restrict__ bs) {
    int g = blockIdx.x;
    __shared__ int sh[256];
    int v = (threadIdx.x < SCB) ? bs[g * 256 + threadIdx.x] : 0;
    sh[threadIdx.x] = v;
    __syncthreads();
#pragma unroll
    for (int o = 1; o < 256; o <<= 1) {
        int t = (threadIdx.x >= o) ? sh[threadIdx.x - o] : 0;
        __syncthreads();
        sh[threadIdx.x] += t;
        __syncthreads();
    }
    bs[g * 256 + threadIdx.x] = sh[threadIdx.x] - v;  // exclusive
}

__global__ void scan3_k(const int* __restrict__ cnt, int* __restrict__ rp,
                        const int* __restrict__ bs, int* __restrict__ wp) {
    int g = blockIdx.y;
    int idx = blockIdx.x * 512 + threadIdx.x;
    if (idx < Nn) {
        int ex = rp[g * (Nn + 1) + idx] - cnt[g * Nn + idx] + bs[g * 256 + blockIdx.x];
        rp[g * (Nn + 1) + idx] = ex;
        wp[g * Nn + idx] = ex;
    }
    if (idx == 0) rp[g * (Nn + 1) + Nn] = Ee;
}

__global__ void fill_k(const int* __restrict__ e0, const int* __restrict__ e1,
                       int* __restrict__ wp, int* __restrict__ col) {
    int e = blockIdx.x * blockDim.x + threadIdx.x;
    if (e >= Ee) return;
    {
        int dst = __ldg(e0 + Ee + e);
        int pos = atomicAdd(wp + dst, 1);
        col[pos] = __ldg(e0 + e);
    }
    {
        int dst = __ldg(e1 + Ee + e);
        int pos = atomicAdd(wp + Nn + dst, 1);
        col[Ee + pos] = __ldg(e1 + e);
    }
}

__global__ void dinv2_k(const int* __restrict__ rp, float* __restrict__ d) {
    int g = blockIdx.y;
    int i = blockIdx.x * blockDim.x + threadIdx.x;
    if (i < Nn) {
        int deg = rp[g * (Nn + 1) + i + 1] - rp[g * (Nn + 1) + i];
        d[g * Nn + i] = rsqrtf((float)deg + 1.f);
    }
}

// ---------------------------------------------------------------------------
// CSR aggregation + fused GCN epilogue, both graphs (grid.y = g):
//   H[n,:] = relu(dinv[n]*(sum_{src in adj(n)} Y[src,:] + Y[n,:]) + bias[:])
// ---------------------------------------------------------------------------
__global__ __launch_bounds__(256) void aggfuse2_k(
    const float* __restrict__ yb, const int* __restrict__ rpb,
    const int* __restrict__ colb, const float* __restrict__ Dinvb,
    const float* __restrict__ bias0, const float* __restrict__ bias1,
    float* __restrict__ Hb) {
    int g = blockIdx.y;
    const float* y = yb + (size_t)g * Nn * 64;
    const int* rp = rpb + g * (Nn + 1);
    const int* col = colb + (size_t)g * Ee;
    const float* bias = g ? bias1 : bias0;
    float* out = Hb + (size_t)g * Nn * 64;

    int node = blockIdx.x * 16 + (threadIdx.x >> 4);
    if (node >= Nn) return;
    int j = (threadIdx.x & 15) * 4;
    int b = __ldg(rp + node), e = __ldg(rp + node + 1);

    float4 s0 = *(const float4*)(y + (size_t)node * 64 + j);   // self term
    float4 s1 = make_float4(0.f, 0.f, 0.f, 0.f);
    int i = b;
    for (; i + 2 <= e; i += 2) {
        int a0 = __ldg(col + i), a1 = __ldg(col + i + 1);
        float4 v0 = *(const float4*)(y + (size_t)a0 * 64 + j);
        float4 v1 = *(const float4*)(y + (size_t)a1 * 64 + j);
        s0.x += v0.x; s0.y += v0.y; s0.z += v0.z; s0.w += v0.w;
        s1.x += v1.x; s1.y += v1.y; s1.z += v1.z; s1.w += v1.w;
    }
    if (i < e) {
        int a0 = __ldg(col + i);
        float4 v0 = *(const float4*)(y + (size_t)a0 * 64 + j);
        s0.x += v0.x; s0.y += v0.y; s0.z += v0.z; s0.w += v0.w;
    }
    s0.x += s1.x; s0.y += s1.y; s0.z += s1.z; s0.w += s1.w;

    float dv = __ldg(Dinvb + g * Nn + node);
    float4 bv = __ldg((const float4*)(bias + j));
    float4 o;
    o.x = fmaxf(fmaf(dv, s0.x, bv.x), 0.f);
    o.y = fmaxf(fmaf(dv, s0.y, bv.y), 0.f);
    o.z = fmaxf(fmaf(dv, s0.z, bv.z), 0.f);
    o.w = fmaxf(fmaf(dv, s0.w, bv.w), 0.f);
    *(float4*)(out + (size_t)node * 64 + j) = o;
}

// ---------------------------------------------------------------------------
// Tiny precompute: Wp[g] = w2 @ cw[0];  bp[g] = b2 @ cw[0]
// ---------------------------------------------------------------------------
__global__ void prep_k(const float* __restrict__ w2a, const float* __restrict__ b2a,
                       const float* __restrict__ cwa,
                       const float* __restrict__ w2b, const float* __restrict__ b2b,
                       const float* __restrict__ cwb,
                       float* __restrict__ wp, float* __restrict__ bp) {
    int g = blockIdx.x;
    const float* w2 = g ? w2b : w2a;
    const float* b2 = g ? b2b : b2a;
    const float* cw = g ? cwb : cwa;
    __shared__ float A[4096], B[4096];
    int tid = threadIdx.x;
#pragma unroll
    for (int t = 0; t < 16; t++) {
        A[tid + t * 256] = w2[tid + t * 256];
        B[tid + t * 256] = cw[tid + t * 256];
    }
    __syncthreads();
    float* WP = wp + g * 4096;
#pragma unroll
    for (int t = 0; t < 16; t++) {
        int idx = tid + t * 256;
        int i = idx >> 6, j = idx & 63;
        float s = 0.f;
#pragma unroll 16
        for (int k = 0; k < 64; k++) s = fmaf(A[i * 64 + k], B[k * 64 + j], s);
        WP[idx] = s;
    }
    if (tid < 64) {
        float s = 0.f;
        for (int k = 0; k < 64; k++) s = fmaf(b2[k], B[k * 64 + tid], s);
        bp[g * 64 + tid] = s;
    }
}

// ---------------------------------------------------------------------------
extern "C" void kernel_launch(void* const* d_in, const int* in_sizes, int n_in,
                              void* d_out, int out_size) {
    const float* xin[2] = {(const float*)d_in[0], (const float*)d_in[1]};
    const int* ei[2]    = {(const int*)d_in[2], (const int*)d_in[3]};
    const float* ew1[2] = {(const float*)d_in[4],  (const float*)d_in[10]};
    const float* eb1[2] = {(const float*)d_in[5],  (const float*)d_in[11]};
    const float* ew2[2] = {(const float*)d_in[6],  (const float*)d_in[12]};
    const float* eb2[2] = {(const float*)d_in[7],  (const float*)d_in[13]};
    const float* cw[2]  = {(const float*)d_in[8],  (const float*)d_in[14]};
    const float* cb[2]  = {(const float*)d_in[9],  (const float*)d_in[15]};
    const float* fw1 = (const float*)d_in[16];
    const float* fb1 = (const float*)d_in[17];
    const float* fw2 = (const float*)d_in[18];
    const float* fb2 = (const float*)d_in[19];
    const float* ow  = (const float*)d_in[20];
    const float* obv = (const float*)d_in[21];
    const float* clw = (const float*)d_in[22];
    const float* clb = (const float*)d_in[23];

    float *Yb, *Hb, *Db, *Wp, *bp;
    int *cnt, *rp, *wpp, *colp, *bs;
    cudaGetSymbolAddress((void**)&Yb, g_Yb);
    cudaGetSymbolAddress((void**)&Hb, g_Hb);
    cudaGetSymbolAddress((void**)&Db, g_D);
    cudaGetSymbolAddress((void**)&Wp, g_Wp);
    cudaGetSymbolAddress((void**)&bp, g_bp);
    cudaGetSymbolAddress((void**)&cnt, g_cnt);
    cudaGetSymbolAddress((void**)&rp, g_rp);
    cudaGetSymbolAddress((void**)&wpp, g_wp);
    cudaGetSymbolAddress((void**)&colp, g_col);
    cudaGetSymbolAddress((void**)&bs, g_bs);

    // Opt-in to >48KB dynamic smem (idempotent host calls, graph-safe)
    cudaFuncSetAttribute(frontT_k,  cudaFuncAttributeMaxDynamicSharedMemorySize, SMEM_BYTES);
    cudaFuncSetAttribute(gcnT_k,    cudaFuncAttributeMaxDynamicSharedMemorySize, SMEM_BYTES);
    cudaFuncSetAttribute(fushead_k, cudaFuncAttributeMaxDynamicSharedMemorySize, SMEM_BYTES);

    // ---- CSR build (both graphs) ----
    cudaMemsetAsync(cnt, 0, 2 * Nn * sizeof(int));
    hist_k<<<(Ee + 255) / 256, 256>>>(ei[0], ei[1], cnt);
    scan1_k<<<dim3(SCB, 2), 512>>>(cnt, rp, bs);
    scan2_k<<<2, 256>>>(bs);
    scan3_k<<<dim3(SCB, 2), 512>>>(cnt, rp, bs, wpp);
    fill_k<<<(Ee + 255) / 256, 256>>>(ei[0], ei[1], wpp, colp);
    dinv2_k<<<dim3((Nn + 255) / 256, 2), 256>>>(rp, Db);
    prep_k<<<2, 256>>>(ew2[0], eb2[0], cw[0], ew2[1], eb2[1], cw[1], Wp, bp);

    const int AGB = (Nn + 15) / 16;
    const dim3 G2(GB2, 2), A2(AGB, 2);

    // Front (both graphs): Y = (relu(x@w1+b1) @ Wp + bp) * dinv
    frontT_k<<<G2, 256, SMEM_BYTES>>>(xin[0], xin[1], ew1[0], ew1[1], eb1[0], eb1[1],
                                      Wp, bp, Db, Yb);
    aggfuse2_k<<<A2, 256>>>(Yb, rp, colp, Db, cb[0], cb[1], Hb);

    // GCN layer 1: Y = (H @ cw[1]) * dinv
    gcnT_k<<<G2, 256, SMEM_BYTES>>>(Hb, cw[0] + 4096, cw[1] + 4096, Db, Yb);
    aggfuse2_k<<<A2, 256>>>(Yb, rp, colp, Db, cb[0] + 64, cb[1] + 64, Hb);

    // GCN layer 2: Y = (H @ cw[2]) * dinv
    gcnT_k<<<G2, 256, SMEM_BYTES>>>(Hb, cw[0] + 8192, cw[1] + 8192, Db, Yb);
    aggfuse2_k<<<A2, 256>>>(Yb, rp, colp, Db, cb[0] + 128, cb[1] + 128, Hb);

    // Fused fusion1 + fusion2 + heads (F never touches global memory)
    fushead_k<<<GB2, 256, SMEM_BYTES>>>(Hb, fw1, fb1, fw2, fb2, ow, obv, clw, clb,
                                        (float*)d_out, (float*)d_out + (size_t)Nn * 32);
}

// round 16
// speedup vs baseline: 1.2029x; 1.0726x over previous
#include <cuda_runtime.h>
#include <cstdint>

#define Nn 100000
#define Ee 1000000
#define GB2 ((Nn + 127) / 128)     /* 782 gemm blocks per graph */
#define SCB 196                    /* scan blocks: ceil(Nn/512) */

#define XSTR 68                    /* Xs row stride: lane bank = 4*gid+tig, conflict-free */
#define WSTR 68
#define SM_X (128 * XSTR)          /* 8704 floats */
#define SM_W (64 * WSTR)           /* 4352 floats */
#define OFF_W1S (SM_X + SM_W)
#define OFF_B1S (OFF_W1S + 256)
#define SMEM_WORDS (OFF_B1S + 64)
#define SMEM_BYTES (SMEM_WORDS * 4)    /* 53504 B */

// Scratch (device globals — no runtime allocation allowed)
__device__ float g_Yb[2][(size_t)Nn * 64];
__device__ float g_Hb[2][(size_t)Nn * 64];
__device__ float g_D[2][Nn];
__device__ float g_Wp[2][64 * 64];          // w2 @ W0
__device__ float g_bp[2][64];               // b2 @ W0
// CSR scratch
__device__ int g_cnt[2][Nn];
__device__ int g_rp[2][Nn + 1];
__device__ int g_wp[2][Nn];
__device__ int g_col[2][Ee];
__device__ int g_bs[2][256];

// ---------------------------------------------------------------------------
// tf32 helpers
// ---------------------------------------------------------------------------
__device__ __forceinline__ void split_tf32(float f, uint32_t& hi, uint32_t& lo) {
    asm("cvt.rna.tf32.f32 %0, %1;" : "=r"(hi) : "f"(f));
    float d = f - __uint_as_float(hi);
    asm("cvt.rna.tf32.f32 %0, %1;" : "=r"(lo) : "f"(d));
}

__device__ __forceinline__ void mma_tf32(float c[4], const uint32_t a[4], const uint32_t b[2]) {
    asm("mma.sync.aligned.m16n8k8.row.col.f32.tf32.tf32.f32 "
        "{%0,%1,%2,%3}, {%4,%5,%6,%7}, {%8,%9}, {%0,%1,%2,%3};"
        : "+f"(c[0]), "+f"(c[1]), "+f"(c[2]), "+f"(c[3])
        : "r"(a[0]), "r"(a[1]), "r"(a[2]), "r"(a[3]), "r"(b[0]), "r"(b[1]));
}

// ---------------------------------------------------------------------------
// Tensor-core GEMM body (R10 config): Xs 128xK64 (stride XSTR), Wt col-major
// 64x64 (stride WSTR). 8 warps: 4m x 2n; per warp 2x4 m16n8; 3xTF32.
// ---------------------------------------------------------------------------
__device__ __forceinline__ void tf32_core(const float* Xs, const float* Wt,
                                          int tid, float c_[2][4][4]) {
    int lane = tid & 31, wid = tid >> 5;
    int gid = lane >> 2, tig = lane & 3;
    int m0 = (wid >> 1) * 32;
    int n0 = (wid & 1) * 32;

#pragma unroll
    for (int k0 = 0; k0 < 64; k0 += 8) {
        uint32_t ab[2][4], as_[2][4];
#pragma unroll
        for (int i = 0; i < 2; i++) {
            const float* base = Xs + (m0 + i * 16 + gid) * XSTR + k0 + tig;
            float f0 = base[0];
            float f1 = base[8 * XSTR];
            float f2 = base[4];
            float f3 = base[8 * XSTR + 4];
            split_tf32(f0, ab[i][0], as_[i][0]);
            split_tf32(f1, ab[i][1], as_[i][1]);
            split_tf32(f2, ab[i][2], as_[i][2]);
            split_tf32(f3, ab[i][3], as_[i][3]);
        }
        uint32_t bb[4][2], bs[4][2];
#pragma unroll
        for (int j = 0; j < 4; j++) {
            const float* base = Wt + (n0 + j * 8 + gid) * WSTR + k0 + tig;
            float g0 = base[0];
            float g1 = base[4];
            split_tf32(g0, bb[j][0], bs[j][0]);
            split_tf32(g1, bb[j][1], bs[j][1]);
        }
#pragma unroll
        for (int i = 0; i < 2; i++)
#pragma unroll
            for (int j = 0; j < 4; j++) {
                mma_tf32(c_[i][j], ab[i], bb[j]);
                mma_tf32(c_[i][j], ab[i], bs[j]);
                mma_tf32(c_[i][j], as_[i], bb[j]);
            }
    }
}

// Fill Wt (col-major, stride WSTR) from row-major W[64][64] — 256 threads
__device__ __forceinline__ void fill_wt(float* Wt, const float* __restrict__ W, int tid) {
#pragma unroll
    for (int t = 0; t < 16; t++) {
        int idx = tid + t * 256;
        int k = idx >> 6, n = idx & 63;
        Wt[n * WSTR + k] = __ldg(W + idx);
    }
}

// Fill Xs (stride XSTR) as copy of in[(row0..row0+127)][64] — 256 threads
__device__ __forceinline__ void fill_copy(float* Xs, const float* __restrict__ in,
                                          int tid, int row0) {
#pragma unroll
    for (int t = 0; t < 8; t++) {
        int lin = tid + t * 256;
        int r = lin >> 4, c4 = lin & 15;
        float4 v = make_float4(0.f, 0.f, 0.f, 0.f);
        if (row0 + r < Nn) v = ((const float4*)in)[(size_t)(row0 + r) * 16 + c4];
        *(float4*)(Xs + r * XSTR + c4 * 4) = v;
    }
}

// Epilogue: write (c + bias) * dinv to global out (bias/dinv optional)
__device__ __forceinline__ void epilogue(const float c_[2][4][4], int tid, int row0,
                                         const float* __restrict__ bias,
                                         const float* __restrict__ dinv,
                                         float* __restrict__ out) {
    int lane = tid & 31, wid = tid >> 5;
    int gid = lane >> 2, tig = lane & 3;
    int m0 = (wid >> 1) * 32;
    int n0 = (wid & 1) * 32;
#pragma unroll
    for (int i = 0; i < 2; i++) {
        int r0 = row0 + m0 + i * 16 + gid;
        int r1 = r0 + 8;
        float d0 = (r0 < Nn && dinv) ? dinv[r0] : 1.f;
        float d1 = (r1 < Nn && dinv) ? dinv[r1] : 1.f;
#pragma unroll
        for (int j = 0; j < 4; j++) {
            int cc = n0 + j * 8 + 2 * tig;
            float bx = 0.f, by = 0.f;
            if (bias) { float2 bv = *(const float2*)(bias + cc); bx = bv.x; by = bv.y; }
            if (r0 < Nn)
                *(float2*)(out + (size_t)r0 * 64 + cc) =
                    make_float2((c_[i][j][0] + bx) * d0, (c_[i][j][1] + by) * d0);
            if (r1 < Nn)
                *(float2*)(out + (size_t)r1 * 64 + cc) =
                    make_float2((c_[i][j][2] + bx) * d1, (c_[i][j][3] + by) * d1);
        }
    }
}

// Fragment write into smem tile (stride XSTR): v = f(c + bias), optional relu
__device__ __forceinline__ void frag_to_smem(const float c_[2][4][4], int tid,
                                             const float* __restrict__ bias,
                                             int doRelu, float* Xs) {
    int lane = tid & 31, wid = tid >> 5;
    int gid = lane >> 2, tig = lane & 3;
    int m0 = (wid >> 1) * 32;
    int n0 = (wid & 1) * 32;
#pragma unroll
    for (int i = 0; i < 2; i++) {
        int lr0 = m0 + i * 16 + gid;
        int lr1 = lr0 + 8;
#pragma unroll
        for (int j = 0; j < 4; j++) {
            int cc = n0 + j * 8 + 2 * tig;
            float2 bv = *(const float2*)(bias + cc);
            float a0 = c_[i][j][0] + bv.x, a1 = c_[i][j][1] + bv.y;
            float a2 = c_[i][j][2] + bv.x, a3 = c_[i][j][3] + bv.y;
            if (doRelu) {
                a0 = fmaxf(a0, 0.f); a1 = fmaxf(a1, 0.f);
                a2 = fmaxf(a2, 0.f); a3 = fmaxf(a3, 0.f);
            }
            *(float2*)(Xs + lr0 * XSTR + cc) = make_float2(a0, a1);
            *(float2*)(Xs + lr1 * XSTR + cc) = make_float2(a2, a3);
        }
    }
}

// ---------------------------------------------------------------------------
// Front GEMM (both graphs): Y = (relu(x@w1+b1) @ Wp + bp) * dinv
// ---------------------------------------------------------------------------
__global__ __launch_bounds__(256) void frontT_k(
    const float* __restrict__ x0, const float* __restrict__ x1,
    const float* __restrict__ w10, const float* __restrict__ w11,
    const float* __restrict__ b10, const float* __restrict__ b11,
    const float* __restrict__ Wpb, const float* __restrict__ bpb,
    const float* __restrict__ Dinvb, float* __restrict__ Yb) {
    extern __shared__ float sm[];
    float* Xs = sm;
    float* Wt = sm + SM_X;
    float* W1s = sm + OFF_W1S;
    float* B1s = sm + OFF_B1S;

    int g = blockIdx.y;
    const float* x  = g ? x1 : x0;
    const float* w1 = g ? w11 : w10;
    const float* b1 = g ? b11 : b10;
    int tid = threadIdx.x;
    int row0 = blockIdx.x * 128;

    fill_wt(Wt, Wpb + g * 4096, tid);
    if (tid < 256) W1s[tid] = __ldg(w1 + tid);
    if (tid < 64)  B1s[tid] = __ldg(b1 + tid);
    __syncthreads();

#pragma unroll
    for (int t = 0; t < 8; t++) {
        int lin = tid + t * 256;
        int r = lin >> 4;
        int c = (lin & 15) * 4;
        float4 v = make_float4(0.f, 0.f, 0.f, 0.f);
        if (row0 + r < Nn) {
            float4 xv = __ldg((const float4*)x + (row0 + r));
            v.x = fmaxf(B1s[c+0] + xv.x*W1s[c+0] + xv.y*W1s[64+c+0] + xv.z*W1s[128+c+0] + xv.w*W1s[192+c+0], 0.f);
            v.y = fmaxf(B1s[c+1] + xv.x*W1s[c+1] + xv.y*W1s[64+c+1] + xv.z*W1s[128+c+1] + xv.w*W1s[192+c+1], 0.f);
            v.z = fmaxf(B1s[c+2] + xv.x*W1s[c+2] + xv.y*W1s[64+c+2] + xv.z*W1s[128+c+2] + xv.w*W1s[192+c+2], 0.f);
            v.w = fmaxf(B1s[c+3] + xv.x*W1s[c+3] + xv.y*W1s[64+c+3] + xv.z*W1s[128+c+3] + xv.w*W1s[192+c+3], 0.f);
        }
        *(float4*)(Xs + r * XSTR + c) = v;
    }
    __syncthreads();

    float c_[2][4][4];
#pragma unroll
    for (int i = 0; i < 2; i++)
#pragma unroll
        for (int j = 0; j < 4; j++)
#pragma unroll
            for (int q = 0; q < 4; q++) c_[i][j][q] = 0.f;

    tf32_core(Xs, Wt, tid, c_);
    epilogue(c_, tid, row0, bpb + g * 64, Dinvb + g * Nn,
             Yb + (size_t)g * Nn * 64);
}

// ---------------------------------------------------------------------------
// GCN GEMM (both graphs): Y = (H @ W) * dinv
// ---------------------------------------------------------------------------
__global__ __launch_bounds__(256) void gcnT_k(
    const float* __restrict__ Hb,
    const float* __restrict__ W0, const float* __restrict__ W1,
    const float* __restrict__ Dinvb, float* __restrict__ Yb) {
    extern __shared__ float sm[];
    float* Xs = sm;
    float* Wt = sm + SM_X;

    int g = blockIdx.y;
    int tid = threadIdx.x;
    int row0 = blockIdx.x * 128;

    fill_wt(Wt, g ? W1 : W0, tid);
    fill_copy(Xs, Hb + (size_t)g * Nn * 64, tid, row0);
    __syncthreads();

    float c_[2][4][4];
#pragma unroll
    for (int i = 0; i < 2; i++)
#pragma unroll
        for (int j = 0; j < 4; j++)
#pragma unroll
            for (int q = 0; q < 4; q++) c_[i][j][q] = 0.f;

    tf32_core(Xs, Wt, tid, c_);
    epilogue(c_, tid, row0, nullptr, Dinvb + g * Nn, Yb + (size_t)g * Nn * 64);
}

// ---------------------------------------------------------------------------
// Fused fusion + head kernel (head on tensor pipe):
//   F = [H_g0, H_g1] @ fw1 + fb1         (K=128, two tf32 phases)
//   fused = relu(F) @ fw2 + fb2          (tf32 phase, smem-resident)
//   [outF | outT] = fused @ [ow | cw]    (tf32 phase with packed weights)
// ---------------------------------------------------------------------------
__global__ __launch_bounds__(256) void fushead_k(
    const float* __restrict__ Hb, const float* __restrict__ fw1,
    const float* __restrict__ fb1, const float* __restrict__ fw2,
    const float* __restrict__ fb2, const float* __restrict__ ow,
    const float* __restrict__ ob, const float* __restrict__ cw,
    const float* __restrict__ cb,
    float* __restrict__ outF, float* __restrict__ outT) {
    extern __shared__ float sm[];
    float* Xs = sm;
    float* Wt = sm + SM_X;

    int tid = threadIdx.x;
    int row0 = blockIdx.x * 128;

    // ---- fusion layer 1: F (K=128 via two phases) ----
    float c_[2][4][4];
#pragma unroll
    for (int i = 0; i < 2; i++)
#pragma unroll
        for (int j = 0; j < 4; j++)
#pragma unroll
            for (int q = 0; q < 4; q++) c_[i][j][q] = 0.f;

#pragma unroll
    for (int ph = 0; ph < 2; ph++) {
        fill_wt(Wt, fw1 + ph * 4096, tid);
        fill_copy(Xs, Hb + (size_t)ph * Nn * 64, tid, row0);
        __syncthreads();
        tf32_core(Xs, Wt, tid, c_);
        __syncthreads();
    }

    // ---- relu(F + fb1) -> Xs; fw2 -> Wt ----
    frag_to_smem(c_, tid, fb1, 1, Xs);
    fill_wt(Wt, fw2, tid);
    __syncthreads();

    // ---- fusion layer 2: fused = relu(F) @ fw2 ----
#pragma unroll
    for (int i = 0; i < 2; i++)
#pragma unroll
        for (int j = 0; j < 4; j++)
#pragma unroll
            for (int q = 0; q < 4; q++) c_[i][j][q] = 0.f;
    tf32_core(Xs, Wt, tid, c_);
    __syncthreads();

    // ---- fused + fb2 -> Xs; packed head weights [ow | cw | 0] -> Wt ----
    frag_to_smem(c_, tid, fb2, 0, Xs);
#pragma unroll
    for (int t = 0; t < 16; t++) {
        int idx = tid + t * 256;
        int k = idx >> 6, n = idx & 63;
        float v = 0.f;
        if (n < 32)      v = __ldg(ow + k * 32 + n);
        else if (n < 34) v = __ldg(cw + k * 2 + (n - 32));
        Wt[n * WSTR + k] = v;
    }
    __syncthreads();

    // ---- head GEMM on tensor pipe: [outF | outT] = fused @ [ow | cw] ----
#pragma unroll
    for (int i = 0; i < 2; i++)
#pragma unroll
        for (int j = 0; j < 4; j++)
#pragma unroll
            for (int q = 0; q < 4; q++) c_[i][j][q] = 0.f;
    tf32_core(Xs, Wt, tid, c_);

    // ---- fragment epilogue: cols<32 -> outF(+ob); col-pair 32 -> outT(+cb) ----
    {
        int lane = tid & 31, wid = tid >> 5;
        int gid = lane >> 2, tig = lane & 3;
        int m0 = (wid >> 1) * 32;
        int n0 = (wid & 1) * 32;
#pragma unroll
        for (int i = 0; i < 2; i++) {
            int r0 = row0 + m0 + i * 16 + gid;
            int r1 = r0 + 8;
#pragma unroll
            for (int j = 0; j < 4; j++) {
                int cc = n0 + j * 8 + 2 * tig;
                if (cc < 32) {
                    float2 bv = *(const float2*)(ob + cc);
                    if (r0 < Nn)
                        *(float2*)(outF + (size_t)r0 * 32 + cc) =
                            make_float2(c_[i][j][0] + bv.x, c_[i][j][1] + bv.y);
                    if (r1 < Nn)
                        *(float2*)(outF + (size_t)r1 * 32 + cc) =
                            make_float2(c_[i][j][2] + bv.x, c_[i][j][3] + bv.y);
                } else if (cc == 32) {
                    float b0 = __ldg(cb), b1 = __ldg(cb + 1);
                    if (r0 < Nn)
                        *(float2*)(outT + (size_t)r0 * 2) =
                            make_float2(c_[i][j][0] + b0, c_[i][j][1] + b1);
                    if (r1 < Nn)
                        *(float2*)(outT + (size_t)r1 * 2) =
                            make_float2(c_[i][j][2] + b0, c_[i][j][3] + b1);
                }
            }
        }
    }
}

// ---------------------------------------------------------------------------
// CSR build: histogram -> exclusive scan -> placement fill
// ---------------------------------------------------------------------------
__global__ void hist_k(const int* __restrict__ e0, const int* __restrict__ e1,
                       int* __restrict__ c) {
    int e = blockIdx.x * blockDim.x + threadIdx.x;
    if (e < Ee) {
        atomicAdd(c + __ldg(e0 + Ee + e), 1);
        atomicAdd(c + Nn + __ldg(e1 + Ee + e), 1);
    }
}

__global__ void scan1_k(const int* __restrict__ cnt, int* __restrict__ rp,
                        int* __restrict__ bs) {
    int g = blockIdx.y;
    __shared__ int sh[512];
    int idx = blockIdx.x * 512 + threadIdx.x;
    int v = (idx < Nn) ? cnt[g * Nn + idx] : 0;
    sh[threadIdx.x] = v;
    __syncthreads();
#pragma unroll
    for (int o = 1; o < 512; o <<= 1) {
        int t = (threadIdx.x >= o) ? sh[threadIdx.x - o] : 0;
        __syncthreads();
        sh[threadIdx.x] += t;
        __syncthreads();
    }
    if (idx < Nn) rp[g * (Nn + 1) + idx] = sh[threadIdx.x];
    if (threadIdx.x == 511) bs[g * 256 + blockIdx.x] = sh[511];
}

__global__ void scan2_k(int* __restrict__ bs) {
    int g = blockIdx.x;
    __shared__ int sh[256];
    int v = (threadIdx.x < SCB) ? bs[g * 256 + threadIdx.x] : 0;
    sh[threadIdx.x] = v;
    __syncthreads();
#pragma unroll
    for (int o = 1; o < 256; o <<= 1) {
        int t = (threadIdx.x >= o) ? sh[threadIdx.x - o] : 0;
        __syncthreads();
        sh[threadIdx.x] += t;
        __syncthreads();
    }
    bs[g * 256 + threadIdx.x] = sh[threadIdx.x] - v;  // exclusive
}

// scan3 + dinv fused: deg = cnt[idx] is already loaded here
__global__ void scan3_k(const int* __restrict__ cnt, int* __restrict__ rp,
                        const int* __restrict__ bs, int* __restrict__ wp,
                        float* __restrict__ d) {
    int g = blockIdx.y;
    int idx = blockIdx.x * 512 + threadIdx.x;
    if (idx < Nn) {
        int deg = cnt[g * Nn + idx];
        int ex = rp[g * (Nn + 1) + idx] - deg + bs[g * 256 + blockIdx.x];
        rp[g * (Nn + 1) + idx] = ex;
        wp[g * Nn + idx] = ex;
        d[g * Nn + idx] = rsqrtf((float)deg + 1.f);
    }
    if (idx == 0) rp[g * (Nn + 1) + Nn] = Ee;
}

__global__ void fill_k(const int* __restrict__ e0, const int* __restrict__ e1,
                       int* __restrict__ wp, int* __restrict__ col) {
    int e = blockIdx.x * blockDim.x + threadIdx.x;
    if (e >= Ee) return;
    {
        int dst = __ldg(e0 + Ee + e);
        int pos = atomicAdd(wp + dst, 1);
        col[pos] = __ldg(e0 + e);
    }
    {
        int dst = __ldg(e1 + Ee + e);
        int pos = atomicAdd(wp + Nn + dst, 1);
        col[Ee + pos] = __ldg(e1 + e);
    }
}

// ---------------------------------------------------------------------------
// CSR aggregation + fused GCN epilogue, both graphs (grid.y = g):
//   H[n,:] = relu(dinv[n]*(sum_{src in adj(n)} Y[src,:] + Y[n,:]) + bias[:])
// ---------------------------------------------------------------------------
__global__ __launch_bounds__(256) void aggfuse2_k(
    const float* __restrict__ yb, const int* __restrict__ rpb,
    const int* __restrict__ colb, const float* __restrict__ Dinvb,
    const float* __restrict__ bias0, const float* __restrict__ bias1,
    float* __restrict__ Hb) {
    int g = blockIdx.y;
    const float* y = yb + (size_t)g * Nn * 64;
    const int* rp = rpb + g * (Nn + 1);
    const int* col = colb + (size_t)g * Ee;
    const float* bias = g ? bias1 : bias0;
    float* out = Hb + (size_t)g * Nn * 64;

    int node = blockIdx.x * 16 + (threadIdx.x >> 4);
    if (node >= Nn) return;
    int j = (threadIdx.x & 15) * 4;
    int b = __ldg(rp + node), e = __ldg(rp + node + 1);

    float4 s0 = *(const float4*)(y + (size_t)node * 64 + j);   // self term
    float4 s1 = make_float4(0.f, 0.f, 0.f, 0.f);
    int i = b;
    for (; i + 2 <= e; i += 2) {
        int a0 = __ldg(col + i), a1 = __ldg(col + i + 1);
        float4 v0 = *(const float4*)(y + (size_t)a0 * 64 + j);
        float4 v1 = *(const float4*)(y + (size_t)a1 * 64 + j);
        s0.x += v0.x; s0.y += v0.y; s0.z += v0.z; s0.w += v0.w;
        s1.x += v1.x; s1.y += v1.y; s1.z += v1.z; s1.w += v1.w;
    }
    if (i < e) {
        int a0 = __ldg(col + i);
        float4 v0 = *(const float4*)(y + (size_t)a0 * 64 + j);
        s0.x += v0.x; s0.y += v0.y; s0.z += v0.z; s0.w += v0.w;
    }
    s0.x += s1.x; s0.y += s1.y; s0.z += s1.z; s0.w += s1.w;

    float dv = __ldg(Dinvb + g * Nn + node);
    float4 bv = __ldg((const float4*)(bias + j));
    float4 o;
    o.x = fmaxf(fmaf(dv, s0.x, bv.x), 0.f);
    o.y = fmaxf(fmaf(dv, s0.y, bv.y), 0.f);
    o.z = fmaxf(fmaf(dv, s0.z, bv.z), 0.f);
    o.w = fmaxf(fmaf(dv, s0.w, bv.w), 0.f);
    *(float4*)(out + (size_t)node * 64 + j) = o;
}

// ---------------------------------------------------------------------------
// Tiny precompute: Wp[g] = w2 @ cw[0];  bp[g] = b2 @ cw[0]
// ---------------------------------------------------------------------------
__global__ void prep_k(const float* __restrict__ w2a, const float* __restrict__ b2a,
                       const float* __restrict__ cwa,
                       const float* __restrict__ w2b, const float* __restrict__ b2b,
                       const float* __restrict__ cwb,
                       float* __restrict__ wp, float* __restrict__ bp) {
    int g = blockIdx.x;
    const float* w2 = g ? w2b : w2a;
    const float* b2 = g ? b2b : b2a;
    const float* cw = g ? cwb : cwa;
    __shared__ float A[4096], B[4096];
    int tid = threadIdx.x;
#pragma unroll
    for (int t = 0; t < 16; t++) {
        A[tid + t * 256] = w2[tid + t * 256];
        B[tid + t * 256] = cw[tid + t * 256];
    }
    __syncthreads();
    float* WP = wp + g * 4096;
#pragma unroll
    for (int t = 0; t < 16; t++) {
        int idx = tid + t * 256;
        int i = idx >> 6, j = idx & 63;
        float s = 0.f;
#pragma unroll 16
        for (int k = 0; k < 64; k++) s = fmaf(A[i * 64 + k], B[k * 64 + j], s);
        WP[idx] = s;
    }
    if (tid < 64) {
        float s = 0.f;
        for (int k = 0; k < 64; k++) s = fmaf(b2[k], B[k * 64 + tid], s);
        bp[g * 64 + tid] = s;
    }
}

// ---------------------------------------------------------------------------
extern "C" void kernel_launch(void* const* d_in, const int* in_sizes, int n_in,
                              void* d_out, int out_size) {
    const float* xin[2] = {(const float*)d_in[0], (const float*)d_in[1]};
    const int* ei[2]    = {(const int*)d_in[2], (const int*)d_in[3]};
    const float* ew1[2] = {(const float*)d_in[4],  (const float*)d_in[10]};
    const float* eb1[2] = {(const float*)d_in[5],  (const float*)d_in[11]};
    const float* ew2[2] = {(const float*)d_in[6],  (const float*)d_in[12]};
    const float* eb2[2] = {(const float*)d_in[7],  (const float*)d_in[13]};
    const float* cw[2]  = {(const float*)d_in[8],  (const float*)d_in[14]};
    const float* cb[2]  = {(const float*)d_in[9],  (const float*)d_in[15]};
    const float* fw1 = (const float*)d_in[16];
    const float* fb1 = (const float*)d_in[17];
    const float* fw2 = (const float*)d_in[18];
    const float* fb2 = (const float*)d_in[19];
    const float* ow  = (const float*)d_in[20];
    const float* obv = (const float*)d_in[21];
    const float* clw = (const float*)d_in[22];
    const float* clb = (const float*)d_in[23];

    float *Yb, *Hb, *Db, *Wp, *bp;
    int *cnt, *rp, *wpp, *colp, *bs;
    cudaGetSymbolAddress((void**)&Yb, g_Yb);
    cudaGetSymbolAddress((void**)&Hb, g_Hb);
    cudaGetSymbolAddress((void**)&Db, g_D);
    cudaGetSymbolAddress((void**)&Wp, g_Wp);
    cudaGetSymbolAddress((void**)&bp, g_bp);
    cudaGetSymbolAddress((void**)&cnt, g_cnt);
    cudaGetSymbolAddress((void**)&rp, g_rp);
    cudaGetSymbolAddress((void**)&wpp, g_wp);
    cudaGetSymbolAddress((void**)&colp, g_col);
    cudaGetSymbolAddress((void**)&bs, g_bs);

    // Opt-in to >48KB dynamic smem (idempotent host calls, graph-safe)
    cudaFuncSetAttribute(frontT_k,  cudaFuncAttributeMaxDynamicSharedMemorySize, SMEM_BYTES);
    cudaFuncSetAttribute(gcnT_k,    cudaFuncAttributeMaxDynamicSharedMemorySize, SMEM_BYTES);
    cudaFuncSetAttribute(fushead_k, cudaFuncAttributeMaxDynamicSharedMemorySize, SMEM_BYTES);

    // ---- CSR build (both graphs), dinv fused into scan3 ----
    cudaMemsetAsync(cnt, 0, 2 * Nn * sizeof(int));
    hist_k<<<(Ee + 255) / 256, 256>>>(ei[0], ei[1], cnt);
    scan1_k<<<dim3(SCB, 2), 512>>>(cnt, rp, bs);
    scan2_k<<<2, 256>>>(bs);
    scan3_k<<<dim3(SCB, 2), 512>>>(cnt, rp, bs, wpp, Db);
    fill_k<<<(Ee + 255) / 256, 256>>>(ei[0], ei[1], wpp, colp);
    prep_k<<<2, 256>>>(ew2[0], eb2[0], cw[0], ew2[1], eb2[1], cw[1], Wp, bp);

    const int AGB = (Nn + 15) / 16;
    const dim3 G2(GB2, 2), A2(AGB, 2);

    // Front (both graphs): Y = (relu(x@w1+b1) @ Wp + bp) * dinv
    frontT_k<<<G2, 256, SMEM_BYTES>>>(xin[0], xin[1], ew1[0], ew1[1], eb1[0], eb1[1],
                                      Wp, bp, Db, Yb);
    aggfuse2_k<<<A2, 256>>>(Yb, rp, colp, Db, cb[0], cb[1], Hb);

    // GCN layer 1: Y = (H @ cw[1]) * dinv
    gcnT_k<<<G2, 256, SMEM_BYTES>>>(Hb, cw[0] + 4096, cw[1] + 4096, Db, Yb);
    aggfuse2_k<<<A2, 256>>>(Yb, rp, colp, Db, cb[0] + 64, cb[1] + 64, Hb);

    // GCN layer 2: Y = (H @ cw[2]) * dinv
    gcnT_k<<<G2, 256, SMEM_BYTES>>>(Hb, cw[0] + 8192, cw[1] + 8192, Db, Yb);
    aggfuse2_k<<<A2, 256>>>(Yb, rp, colp, Db, cb[0] + 128, cb[1] + 128, Hb);

    // Fused fusion1 + fusion2 + heads (F never in global; head on tensor pipe)
    fushead_k<<<GB2, 256, SMEM_BYTES>>>(Hb, fw1, fb1, fw2, fb2, ow, obv, clw, clb,
                                        (float*)d_out, (float*)d_out + (size_t)Nn * 32);
}